// round 6
// baseline (speedup 1.0000x reference)
#include <cuda_runtime.h>
#include <math.h>

#define GD 160
#define GH 160
#define GW 160
#define GHW (GH * GW)
#define NP 25000
#define RADF 3.0f
#define PATCHN 20

#define TS 16            // tile side
#define TPD 10           // tiles per dim (160/16)
#define NT (TPD*TPD*TPD) // 1000 tiles
#define MAXP 700000      // >= 25000*27 worst case

// fold exp(-0.5*e) into exp2(KLOG2*e)
#define KLOG2 (-0.72134752044448170368f)
// keep contributions with w >= exp(-12)  <=>  e2 >= -12*log2(e)
#define E2T (-17.312340490667560889f)

struct PParams {
    float cz, cy, cx;
    float q00, a01, a02;     // log2-domain quadratic coeffs
    float b11, b22, b12;
    float inv2q;             // 0.5/q00
    float r0, r1, g;         // g = exp2(2*q00)
    int lz, uz, ly, uy, lx, ux, valid;
};

__device__ PParams g_params[NP];
__device__ int tile_cnt[NT];
__device__ int tile_start[NT + 1];
__device__ int tile_cur[NT];
__device__ int pair_g[MAXP];

__device__ __forceinline__ float ex2f(float x) {
    float y;
    asm("ex2.approx.f32 %0, %1;" : "=f"(y) : "f"(x));
    return y;
}

__global__ __launch_bounds__(256) void precompute_kernel(
    const float* __restrict__ centers,
    const float* __restrict__ log_scales,
    const float* __restrict__ quats,
    const float* __restrict__ rho)
{
    const int n = blockIdx.x * blockDim.x + threadIdx.x;
    if (n < NT) tile_cnt[n] = 0;          // zero bin counters (runs before count)
    if (n >= NP) return;

    PParams p;

    const float cz = centers[n * 3 + 0] * (float)(GD - 1);
    const float cy = centers[n * 3 + 1] * (float)(GH - 1);
    const float cx = centers[n * 3 + 2] * (float)(GW - 1);

    const float s0 = expf(log_scales[n * 3 + 0]);
    const float s1 = expf(log_scales[n * 3 + 1]);
    const float s2 = expf(log_scales[n * 3 + 2]);

    const float r0v = rho[n * 2 + 0];
    const float r1v = rho[n * 2 + 1];

    const float smax = fmaxf(s0, fmaxf(s1, s2));
    const float rad  = smax * RADF;
    const float amp  = sqrtf(r0v * r0v + r1v * r1v);

    int valid = (amp >= 1e-6f && rad >= 1e-3f);

    const int bz = (int)floorf(cz - rad), by = (int)floorf(cy - rad), bx = (int)floorf(cx - rad);
    const int hz = (int)ceilf(cz + rad),  hy = (int)ceilf(cy + rad),  hx = (int)ceilf(cx + rad);
    const int lz = max(bz, 0), ly = max(by, 0), lx = max(bx, 0);
    const int uz = min(min(hz, GD - 1), bz + PATCHN - 1);
    const int uy = min(min(hy, GH - 1), by + PATCHN - 1);
    const int ux = min(min(hx, GW - 1), bx + PATCHN - 1);
    if (lz > uz || ly > uy || lx > ux) valid = 0;

    p.valid = valid;
    if (valid) {
        float qw = quats[n * 4 + 0], qx = quats[n * 4 + 1];
        float qy = quats[n * 4 + 2], qz = quats[n * 4 + 3];
        float nq = fmaxf(sqrtf(qw * qw + qx * qx + qy * qy + qz * qz), 1e-6f);
        float inq = 1.0f / nq;
        qw *= inq; qx *= inq; qy *= inq; qz *= inq;

        const float ww = qw * qw, xx = qx * qx, yy = qy * qy, zz = qz * qz;
        const float wx = qw * qx, wy = qw * qy, wz = qw * qz;
        const float xy = qx * qy, xz = qx * qz, yz = qy * qz;

        const float R00 = ww + xx - yy - zz, R01 = 2.f * (xy - wz), R02 = 2.f * (xz + wy);
        const float R10 = 2.f * (xy + wz),   R11 = ww - xx + yy - zz, R12 = 2.f * (yz - wx);
        const float R20 = 2.f * (xz - wy),   R21 = 2.f * (yz + wx),   R22 = ww - xx - yy + zz;

        const float c0 = fmaxf(s0, 1e-4f), c1 = fmaxf(s1, 1e-4f), c2 = fmaxf(s2, 1e-4f);
        const float i0 = 1.0f / (c0 * c0), i1 = 1.0f / (c1 * c1), i2 = 1.0f / (c2 * c2);

        const float p00 = R00 * R00 * i0 + R01 * R01 * i1 + R02 * R02 * i2;
        const float p11 = R10 * R10 * i0 + R11 * R11 * i1 + R12 * R12 * i2;
        const float p22 = R20 * R20 * i0 + R21 * R21 * i1 + R22 * R22 * i2;
        const float p01 = R00 * R10 * i0 + R01 * R11 * i1 + R02 * R12 * i2;
        const float p02 = R00 * R20 * i0 + R01 * R21 * i1 + R02 * R22 * i2;
        const float p12 = R10 * R20 * i0 + R11 * R21 * i1 + R12 * R22 * i2;

        const float q00 = KLOG2 * p00;
        p.cz = cz; p.cy = cy; p.cx = cx;
        p.q00 = q00;
        p.a01 = 2.0f * KLOG2 * p01;
        p.a02 = 2.0f * KLOG2 * p02;
        p.b11 = KLOG2 * p11;
        p.b22 = KLOG2 * p22;
        p.b12 = 2.0f * KLOG2 * p12;
        p.inv2q = 0.5f / q00;
        p.r0 = r0v; p.r1 = r1v;
        p.g = exp2f(2.0f * q00);
        p.lz = lz; p.uz = uz; p.ly = ly; p.uy = uy; p.lx = lx; p.ux = ux;
    }
    g_params[n] = p;
}

__global__ __launch_bounds__(256) void count_kernel()
{
    const int n = blockIdx.x * blockDim.x + threadIdx.x;
    if (n >= NP) return;
    const PParams p = g_params[n];
    if (!p.valid) return;
    for (int tz = p.lz >> 4; tz <= (p.uz >> 4); ++tz)
        for (int ty = p.ly >> 4; ty <= (p.uy >> 4); ++ty)
            for (int tx = p.lx >> 4; tx <= (p.ux >> 4); ++tx)
                atomicAdd(&tile_cnt[(tz * TPD + ty) * TPD + tx], 1);
}

__global__ __launch_bounds__(1024) void scan_kernel()
{
    __shared__ int sdata[1024];
    const int tid = threadIdx.x;
    const int v = (tid < NT) ? tile_cnt[tid] : 0;
    sdata[tid] = v;
    __syncthreads();
    for (int off = 1; off < 1024; off <<= 1) {
        int t = (tid >= off) ? sdata[tid - off] : 0;
        __syncthreads();
        sdata[tid] += t;
        __syncthreads();
    }
    if (tid < NT) {
        tile_start[tid + 1] = sdata[tid];       // inclusive
        tile_cur[tid] = sdata[tid] - v;         // exclusive
    }
    if (tid == 0) tile_start[0] = 0;
}

__global__ __launch_bounds__(256) void fill_kernel()
{
    const int n = blockIdx.x * blockDim.x + threadIdx.x;
    if (n >= NP) return;
    const PParams p = g_params[n];
    if (!p.valid) return;
    for (int tz = p.lz >> 4; tz <= (p.uz >> 4); ++tz)
        for (int ty = p.ly >> 4; ty <= (p.uy >> 4); ++ty)
            for (int tx = p.lx >> 4; tx <= (p.ux >> 4); ++tx) {
                const int slot = atomicAdd(&tile_cur[(tz * TPD + ty) * TPD + tx], 1);
                pair_g[slot] = n;
            }
}

__global__ __launch_bounds__(256) void gather_kernel(float* __restrict__ out)
{
    __shared__ float2 acc[TS * 256];   // [z][column], 32 KB; thread owns column tid

    const int tile = blockIdx.x;
    const int tz = tile / (TPD * TPD);
    const int tr = tile - tz * (TPD * TPD);
    const int ty = tr / TPD;
    const int tx = tr - ty * TPD;
    const int Z0 = tz * TS, Y0 = ty * TS, X0 = tx * TS;

    const int tid = threadIdx.x;
    const int Y = Y0 + (tid >> 4);
    const int X = X0 + (tid & 15);

    // zero own slots (strided by 256 -> pure column ownership, no barriers needed)
    #pragma unroll
    for (int zi = 0; zi < TS; ++zi) acc[zi * 256 + tid] = make_float2(0.f, 0.f);

    const int kb = tile_start[tile];
    const int ke = tile_start[tile + 1];

    for (int k = kb; k < ke; ++k) {
        const PParams p = g_params[pair_g[k]];   // uniform broadcast load

        if (X < p.lx || X > p.ux || Y < p.ly || Y > p.uy) continue;

        const float dy = (float)Y - p.cy;
        const float dx = (float)X - p.cx;
        const float qcl  = p.a01 * dy + p.a02 * dx;
        const float qeyx = p.b11 * dy * dy + (p.b22 * dx + p.b12 * dy) * dx;

        const float disc = qcl * qcl - 4.0f * p.q00 * (qeyx - E2T);
        if (disc <= 0.0f) continue;

        const float s  = sqrtf(disc);
        const float za = (-qcl + s) * p.inv2q;
        const float zb = (-qcl - s) * p.inv2q;
        const int z0l = max(max(p.lz, Z0),      (int)ceilf(p.cz + fminf(za, zb)));
        const int z1l = min(min(p.uz, Z0 + TS - 1), (int)floorf(p.cz + fmaxf(za, zb)));
        if (z0l > z1l) continue;

        // geometric recurrence along z (validated: rel_err ~8e-6)
        const float dz0 = (float)z0l - p.cz;
        float w = ex2f(fmaf(dz0, fmaf(p.q00, dz0, qcl), qeyx));
        float m = ex2f(fmaf(p.q00, 2.0f * dz0 + 1.0f, qcl));

        int idx = (z0l - Z0) * 256 + tid;
        for (int Z = z0l; Z <= z1l; ++Z) {
            float2 a = acc[idx];
            a.x = fmaf(w, p.r0, a.x);
            a.y = fmaf(w, p.r1, a.y);
            acc[idx] = a;
            w *= m;
            m *= p.g;
            idx += 256;
        }
    }

    // writeback: tiles partition the volume exactly -> every voxel written once
    float2* __restrict__ o2 = (float2*)out;
    #pragma unroll
    for (int zi = 0; zi < TS; ++zi) {
        const int v = ((Z0 + zi) * GH + Y) * GW + X;
        o2[v] = acc[zi * 256 + tid];
    }
}

extern "C" void kernel_launch(void* const* d_in, const int* in_sizes, int n_in,
                              void* d_out, int out_size) {
    const float* centers    = (const float*)d_in[0];
    const float* log_scales = (const float*)d_in[1];
    const float* quats      = (const float*)d_in[2];
    const float* rho        = (const float*)d_in[3];
    float* out = (float*)d_out;

    const int gb = (NP + 255) / 256;
    precompute_kernel<<<gb, 256>>>(centers, log_scales, quats, rho);
    count_kernel<<<gb, 256>>>();
    scan_kernel<<<1, 1024>>>();
    fill_kernel<<<gb, 256>>>();
    gather_kernel<<<NT, 256>>>(out);
}

// round 7
// speedup vs baseline: 2.2127x; 2.2127x over previous
#include <cuda_runtime.h>
#include <math.h>

#define GD 160
#define GH 160
#define GW 160
#define GHW (GH * GW)
#define NP 25000
#define RADF 3.0f
#define PATCHN 20

// fold exp(-0.5*e) into exp2(KLOG2*e)
#define KLOG2 (-0.72134752044448170368f)
// keep contributions with w >= exp(-9)  <=>  e2 >= -9*log2(e)
#define E2T (-12.984255367251171f)

struct PParams {
    float cz, cy, cx;
    float q00, a01, a02;     // pre-scaled (log2-domain) quadratic coeffs
    float b11, b22, b12;
    float inv2q;             // 0.5/q00
    float r0, r1;
    float g;                 // exp2(2*q00): constant ratio-of-ratios along z
    int lz, uz, ly, lx;
    int nx, nyx, valid;
};

__device__ PParams g_params[NP];

__device__ __forceinline__ float ex2f(float x) {
    float y;
    asm("ex2.approx.f32 %0, %1;" : "=f"(y) : "f"(x));
    return y;
}

__global__ __launch_bounds__(256) void precompute_kernel(
    const float* __restrict__ centers,
    const float* __restrict__ log_scales,
    const float* __restrict__ quats,
    const float* __restrict__ rho)
{
    const int n = blockIdx.x * blockDim.x + threadIdx.x;
    if (n >= NP) return;

    PParams p;

    const float cz = centers[n * 3 + 0] * (float)(GD - 1);
    const float cy = centers[n * 3 + 1] * (float)(GH - 1);
    const float cx = centers[n * 3 + 2] * (float)(GW - 1);

    const float s0 = expf(log_scales[n * 3 + 0]);
    const float s1 = expf(log_scales[n * 3 + 1]);
    const float s2 = expf(log_scales[n * 3 + 2]);

    const float r0v = rho[n * 2 + 0];
    const float r1v = rho[n * 2 + 1];

    const float smax = fmaxf(s0, fmaxf(s1, s2));
    const float rad  = smax * RADF;
    const float amp  = sqrtf(r0v * r0v + r1v * r1v);

    int valid = (amp >= 1e-6f && rad >= 1e-3f);

    const int bz = (int)floorf(cz - rad), by = (int)floorf(cy - rad), bx = (int)floorf(cx - rad);
    const int hz = (int)ceilf(cz + rad),  hy = (int)ceilf(cy + rad),  hx = (int)ceilf(cx + rad);
    const int lz = max(bz, 0), ly = max(by, 0), lx = max(bx, 0);
    const int uz = min(min(hz, GD - 1), bz + PATCHN - 1);
    const int uy = min(min(hy, GH - 1), by + PATCHN - 1);
    const int ux = min(min(hx, GW - 1), bx + PATCHN - 1);
    if (lz > uz || ly > uy || lx > ux) valid = 0;

    p.valid = valid;
    if (valid) {
        float qw = quats[n * 4 + 0], qx = quats[n * 4 + 1];
        float qy = quats[n * 4 + 2], qz = quats[n * 4 + 3];
        float nq = fmaxf(sqrtf(qw * qw + qx * qx + qy * qy + qz * qz), 1e-6f);
        float inq = 1.0f / nq;
        qw *= inq; qx *= inq; qy *= inq; qz *= inq;

        const float ww = qw * qw, xx = qx * qx, yy = qy * qy, zz = qz * qz;
        const float wx = qw * qx, wy = qw * qy, wz = qw * qz;
        const float xy = qx * qy, xz = qx * qz, yz = qy * qz;

        const float R00 = ww + xx - yy - zz, R01 = 2.f * (xy - wz), R02 = 2.f * (xz + wy);
        const float R10 = 2.f * (xy + wz),   R11 = ww - xx + yy - zz, R12 = 2.f * (yz - wx);
        const float R20 = 2.f * (xz - wy),   R21 = 2.f * (yz + wx),   R22 = ww - xx - yy + zz;

        const float c0 = fmaxf(s0, 1e-4f), c1 = fmaxf(s1, 1e-4f), c2 = fmaxf(s2, 1e-4f);
        const float i0 = 1.0f / (c0 * c0), i1 = 1.0f / (c1 * c1), i2 = 1.0f / (c2 * c2);

        const float p00 = R00 * R00 * i0 + R01 * R01 * i1 + R02 * R02 * i2;
        const float p11 = R10 * R10 * i0 + R11 * R11 * i1 + R12 * R12 * i2;
        const float p22 = R20 * R20 * i0 + R21 * R21 * i1 + R22 * R22 * i2;
        const float p01 = R00 * R10 * i0 + R01 * R11 * i1 + R02 * R12 * i2;
        const float p02 = R00 * R20 * i0 + R01 * R21 * i1 + R02 * R22 * i2;
        const float p12 = R10 * R20 * i0 + R11 * R21 * i1 + R12 * R22 * i2;

        const float q00 = KLOG2 * p00;
        p.cz = cz; p.cy = cy; p.cx = cx;
        p.q00 = q00;
        p.a01 = 2.0f * KLOG2 * p01;
        p.a02 = 2.0f * KLOG2 * p02;
        p.b11 = KLOG2 * p11;
        p.b22 = KLOG2 * p22;
        p.b12 = 2.0f * KLOG2 * p12;
        p.inv2q = 0.5f / q00;
        p.r0 = r0v; p.r1 = r1v;
        p.g = exp2f(2.0f * q00);
        p.lz = lz; p.uz = uz; p.ly = ly; p.lx = lx;
        p.nx = ux - lx + 1;
        p.nyx = (uy - ly + 1) * p.nx;
    }
    g_params[n] = p;
}

__global__ __launch_bounds__(256) void splat_kernel(float* __restrict__ out)
{
    const PParams p = g_params[blockIdx.x];   // broadcast loads, L2-resident
    if (!p.valid) return;

    const int nx = p.nx, nyx = p.nyx;
    const int lz = p.lz, uz = p.uz, ly = p.ly, lx = p.lx;

    for (int t = threadIdx.x; t < nyx; t += blockDim.x) {
        const unsigned mask = __activemask();

        const int iy = t / nx;
        const int ix = t - iy * nx;
        const int Y = ly + iy;
        const int X = lx + ix;
        const float dy = (float)Y - p.cy;
        const float dx = (float)X - p.cx;

        // e2(dz) = q00*dz^2 + qcl*dz + qeyx  (log2-domain; keep e2 >= E2T)
        const float qcl  = p.a01 * dy + p.a02 * dx;
        const float qeyx = p.b11 * dy * dy + (p.b22 * dx + p.b12 * dy) * dx;

        // per-column valid z-range from quadratic roots (q00 < 0)
        int z0l = 0x7FFFFFFF, z1l = -0x7FFFFFFF;
        const float disc = qcl * qcl - 4.0f * p.q00 * (qeyx - E2T);
        if (disc > 0.0f) {
            const float s = sqrtf(disc);
            const float za = (-qcl + s) * p.inv2q;
            const float zb = (-qcl - s) * p.inv2q;
            z0l = max(lz, (int)ceilf(p.cz + fminf(za, zb)));
            z1l = min(uz, (int)floorf(p.cz + fmaxf(za, zb)));
        }

        // geometric recurrence seeds at the lane's own entry z
        float w = 0.0f, m = 0.0f;
        if (z0l <= z1l) {
            const float dz0 = (float)z0l - p.cz;
            const float e0  = fmaf(dz0, fmaf(p.q00, dz0, qcl), qeyx);
            w = ex2f(e0);                                   // weight at z0l
            m = ex2f(fmaf(p.q00, 2.0f * dz0 + 1.0f, qcl));  // ratio w(z+1)/w(z) at z0l
        }

        // warp-union z loop keeps RED addresses coalesced
        const int z0w = __reduce_min_sync(mask, z0l);
        const int z1w = __reduce_max_sync(mask, z1l);
        if (z0w > z1w) continue;

        const int span = z1l - z0l;           // <0 when column empty
        float* dst = out + 2u * (unsigned)(z0w * GHW + Y * GW + X);
        for (int Z = z0w; Z <= z1w; ++Z) {
            if ((unsigned)(Z - z0l) <= (unsigned)span) {
                const float w0 = w * p.r0;
                const float w1 = w * p.r1;
                asm volatile("red.global.add.v2.f32 [%0], {%1, %2};"
                             :: "l"(dst), "f"(w0), "f"(w1)
                             : "memory");
                w *= m;
                m *= p.g;
            }
            dst += 2 * GHW;
        }
    }
}

extern "C" void kernel_launch(void* const* d_in, const int* in_sizes, int n_in,
                              void* d_out, int out_size) {
    const float* centers    = (const float*)d_in[0];
    const float* log_scales = (const float*)d_in[1];
    const float* quats      = (const float*)d_in[2];
    const float* rho        = (const float*)d_in[3];
    float* out = (float*)d_out;

    cudaMemsetAsync(out, 0, (size_t)out_size * sizeof(float), 0);
    precompute_kernel<<<(NP + 255) / 256, 256>>>(centers, log_scales, quats, rho);
    splat_kernel<<<NP, 256>>>(out);
}